// round 4
// baseline (speedup 1.0000x reference)
#include <cuda_runtime.h>

#define N_PRED 20
#define N_LAB  12
#define HALF   10

typedef unsigned long long u64;

__device__ __forceinline__ float sqrt_approx(float x){ float r; asm("sqrt.approx.f32 %0,%1;":"=f"(r):"f"(x)); return r; }
__device__ __forceinline__ float log2_approx(float x){ float r; asm("lg2.approx.f32 %0,%1;":"=f"(r):"f"(x)); return r; }
__device__ __forceinline__ u64 pk2(float a, float b){ u64 r; asm("mov.b64 %0,{%1,%2};":"=l"(r):"f"(a),"f"(b)); return r; }
__device__ __forceinline__ void upk2(u64 v, float&a, float&b){ asm("mov.b64 {%0,%1},%2;":"=f"(a),"=f"(b):"l"(v)); }
__device__ __forceinline__ u64 add2(u64 a,u64 b){ u64 r; asm("add.rn.f32x2 %0,%1,%2;":"=l"(r):"l"(a),"l"(b)); return r; }
__device__ __forceinline__ u64 mul2(u64 a,u64 b){ u64 r; asm("mul.rn.f32x2 %0,%1,%2;":"=l"(r):"l"(a),"l"(b)); return r; }
__device__ __forceinline__ u64 fma2(u64 a,u64 b,u64 c){ u64 r; asm("fma.rn.f32x2 %0,%1,%2,%3;":"=l"(r):"l"(a),"l"(b),"l"(c)); return r; }

__global__ __launch_bounds__(256, 4)
void myloss_kernel(const float4* __restrict__ pred,   // [B, 20, 4]
                   const float4* __restrict__ label,  // [B, 12, 4]
                   float* __restrict__ out, int B)
{
    int t = blockIdx.x * blockDim.x + threadIdx.x;
    int b = t >> 1;          // row
    int h = t & 1;           // half of preds owned by this thread
    if (b >= B) return;

    // 10 preds, coords stored NEGATED and packed as f32x2 pairs so packed
    // adds implement the subtractions. nz also serves as -pz for the epilogue.
    u64 nx[5], ny[5], nz[5];
    float pw[HALF];
    const float4* pr = pred + (long)b * N_PRED + h * HALF;
    #pragma unroll
    for (int q = 0; q < 5; q++) {
        float4 v0 = pr[2*q], v1 = pr[2*q + 1];
        nx[q] = pk2(-v0.x, -v1.x);
        ny[q] = pk2(-v0.y, -v1.y);
        nz[q] = pk2(-v0.z, -v1.z);
        pw[2*q] = v0.w; pw[2*q + 1] = v1.w;
    }

    const float4* lb = label + (long)b * N_LAB;
    float csum = 0.f;       // sum of winning (scaled) costs, identical in both lanes
    u64 cnt = 0ull;         // 4-bit match multiplicity per local pred
    const unsigned MSK = 0xFFFFFFE0u;

    #pragma unroll
    for (int l = 0; l < N_LAB; l++) {
        float4 y = lb[l];   // pair lanes share the sector -> L1 broadcast
        u64 yx = pk2(y.x, y.x), yy = pk2(y.y, y.y), yz = pk2(y.z, y.z);

        float m[5];
        #pragma unroll
        for (int q = 0; q < 5; q++) {
            u64 dx = add2(yx, nx[q]);
            u64 dy = add2(yy, ny[q]);
            u64 d2 = fma2(dx, dx, mul2(dy, dy));
            float a, bb; upk2(d2, a, bb);
            float sa = sqrt_approx(a), sb = sqrt_approx(bb);
            u64 rz = add2(yz, nz[q]) & 0x7FFFFFFF7FFFFFFFull;  // |y.z - pz|
            u64 c2 = add2(pk2(sa, sb), rz);
            float c0, c1; upk2(c2, c0, c1);
            // Embed local index into low 5 mantissa bits: nonneg-float min then
            // gives exact lexicographic (cost, index) = jnp.argmin first-min.
            unsigned u0 = (__float_as_uint(c0) & MSK) | (unsigned)(2*q);
            unsigned u1 = (__float_as_uint(c1) & MSK) | (unsigned)(2*q + 1);
            m[q] = fminf(__uint_as_float(u0), __uint_as_float(u1));
        }
        float w = fminf(fminf(fminf(m[0], m[1]), fminf(m[2], m[3])), m[4]);

        // Cross-thread merge; on exact ties the h==0 half (lower global idx) wins.
        float o  = __shfl_xor_sync(0xffffffffu, w, 1);
        float wc = fminf(w, o);
        bool mine = (h == 0) ? (w <= o) : (w < o);

        csum += __uint_as_float(__float_as_uint(wc) & MSK);
        unsigned loc = __float_as_uint(w) & 31u;          // 0..9
        cnt += mine ? (1ull << (4u * loc)) : 0ull;
    }

    // Epilogue: one log per pred.
    // matched (n>0): contributes -n*log(pw+eps)/12
    // unmatched:     contributes -log(1-pw+eps)/16 + pz/32   (pz = -nz)
    const float EPS = 1e-6f;
    const float LN2 = 0.69314718055994530942f;
    float S = 0.f;
    #pragma unroll
    for (int q = 0; q < 5; q++) {
        float z0, z1; upk2(nz[q], z0, z1);   // negated pz values
        #pragma unroll
        for (int s = 0; s < 2; s++) {
            int j = 2*q + s;
            float nzj = s ? z1 : z0;
            int n = (int)((cnt >> (4*j)) & 15ull);
            float pwj = pw[j];
            bool mt = (n > 0);
            float arg  = mt ? (pwj + EPS) : ((1.0f + EPS) - pwj);
            float lg   = log2_approx(arg);
            float coef = mt ? (-(float)n) * (LN2 / 12.0f) : -(LN2 / 16.0f);
            S = fmaf(coef, lg, S);
            S = fmaf(mt ? 0.f : nzj, -(1.0f / 32.0f), S);
        }
    }
    S += __shfl_xor_sync(0xffffffffu, S, 1);   // partner half

    if (h == 0)
        out[b] = csum * (0.5f / 12.0f) + S;
}

extern "C" void kernel_launch(void* const* d_in, const int* in_sizes, int n_in,
                              void* d_out, int out_size)
{
    const float4* pred  = (const float4*)d_in[0];
    const float4* label = (const float4*)d_in[1];
    float* out = (float*)d_out;
    int B = in_sizes[0] / (N_PRED * 4);

    long threads_total = 2L * B;
    int threads = 256;
    int blocks = (int)((threads_total + threads - 1) / threads);
    myloss_kernel<<<blocks, threads>>>(pred, label, out, B);
}

// round 5
// speedup vs baseline: 1.0398x; 1.0398x over previous
#include <cuda_runtime.h>

#define N_PRED 20
#define N_LAB  12
#define HALF   10

__device__ __forceinline__ float sqrt_approx(float x){ float r; asm("sqrt.approx.f32 %0,%1;":"=f"(r):"f"(x)); return r; }
__device__ __forceinline__ float log2_approx(float x){ float r; asm("lg2.approx.f32 %0,%1;":"=f"(r):"f"(x)); return r; }

__global__ __launch_bounds__(256, 4)
void myloss_kernel(const float4* __restrict__ pred,   // [B, 20, 4]
                   const float4* __restrict__ label,  // [B, 12, 4]
                   float* __restrict__ out, int B)
{
    int t = blockIdx.x * blockDim.x + threadIdx.x;
    int b = t >> 1;          // row
    int h = t & 1;           // half of the preds owned by this thread
    bool valid = (b < B);
    if (!valid) b = B - 1;   // keep full warps converged for the shuffles

    // My 10 preds in registers (contiguous 160B -> coalesced float4 loads).
    float px[HALF], py[HALF], pz[HALF], pw[HALF];
    const float4* pr = pred + (long)b * N_PRED + h * HALF;
    #pragma unroll
    for (int j = 0; j < HALF; j++) {
        float4 v = pr[j];
        px[j] = v.x; py[j] = v.y; pz[j] = v.z; pw[j] = v.w;
    }

    const float4* lb = label + (long)b * N_LAB;
    float csum = 0.f;                 // sum of winning scaled costs (dist+rdiff)
    unsigned long long cnt = 0ull;    // 4-bit match multiplicity per local pred
    const int base4 = 40 * h;         // 4 * my_first_global_index

    #pragma unroll
    for (int l = 0; l < N_LAB; l++) {
        float4 y = lb[l];             // pair lanes share sector -> L1 broadcast

        // 10 candidate keys; low 7 mantissa bits carry 4*global_index so a
        // plain nonneg-float min is an exact lexicographic (cost, idx) min
        // == jnp.argmin first-min tie-break. First tree level fused (5 live).
        float m[5];
        #pragma unroll
        for (int q = 0; q < 5; q++) {
            int j0 = 2*q, j1 = 2*q + 1;
            float dx0 = y.x - px[j0], dy0 = y.y - py[j0];
            float c0  = sqrt_approx(fmaf(dx0, dx0, dy0*dy0)) + fabsf(y.z - pz[j0]);
            float dx1 = y.x - px[j1], dy1 = y.y - py[j1];
            float c1  = sqrt_approx(fmaf(dx1, dx1, dy1*dy1)) + fabsf(y.z - pz[j1]);
            float k0 = __uint_as_float((__float_as_uint(c0) & 0xFFFFFF80u) | (unsigned)(base4 + 4*j0));
            float k1 = __uint_as_float((__float_as_uint(c1) & 0xFFFFFF80u) | (unsigned)(base4 + 4*j1));
            m[q] = fminf(k0, k1);
        }
        float w = fminf(fminf(fminf(m[0], m[1]), fminf(m[2], m[3])), m[4]);

        // Cross-thread merge: global-index-embedded keys are unique, so the
        // float min is the exact global winner and bitwise equality tells
        // whose half it came from.
        float o  = __shfl_xor_sync(0xffffffffu, w, 1);
        float wc = fminf(w, o);
        csum += wc;                                   // (<=127ulp idx noise)
        if (__float_as_uint(wc) == __float_as_uint(w)) {
            int sh = (int)(__float_as_uint(w) & 127u) - base4;  // 4*local_j
            cnt += 1ull << sh;
        }
    }

    // Epilogue: exactly one log per pred.
    //   matched (n>0): -n*log(pw+eps)/12
    //   unmatched:     (-log(1-pw+eps) + 0.5*pz)*0.5/8
    const float EPS = 1e-6f;
    const float LN2 = 0.69314718055994530942f;
    float S = 0.f;
    #pragma unroll
    for (int j = 0; j < HALF; j++) {
        int n = (int)((cnt >> (4*j)) & 15ull);
        bool mt = (n > 0);
        float arg  = mt ? (pw[j] + EPS) : ((1.0f + EPS) - pw[j]);
        float lg   = log2_approx(arg);
        float coef = mt ? ((float)n) * (-LN2 / 12.0f) : (-LN2 / 16.0f);
        S = fmaf(coef, lg, S);
        if (!mt) S = fmaf(pz[j], 1.0f / 32.0f, S);
    }
    S += __shfl_xor_sync(0xffffffffu, S, 1);          // partner half

    if (valid && h == 0)
        out[b] = fmaf(csum, 0.5f / 12.0f, S);
}

extern "C" void kernel_launch(void* const* d_in, const int* in_sizes, int n_in,
                              void* d_out, int out_size)
{
    const float4* pred  = (const float4*)d_in[0];
    const float4* label = (const float4*)d_in[1];
    float* out = (float*)d_out;
    int B = in_sizes[0] / (N_PRED * 4);

    long threads_total = 2L * B;
    int threads = 256;
    int blocks = (int)((threads_total + threads - 1) / threads);
    myloss_kernel<<<blocks, threads>>>(pred, label, out, B);
}